// round 17
// baseline (speedup 1.0000x reference)
#include <cuda_runtime.h>

// Gaussian-tube ray readout.
// out[b, c] = sum_n exp(-2*r2_n - 0.5*max(t_n,0)) * mem[n, c]
//
// R16 evidence (8.7us, nothing saturated, occ 24%, issue 29%): latency-bound
// on (a) serialized guarded-load regions and (b) the 5-stage full-width
// butterfly. This version:
//   A. two-phase: compute all 4 candidate weights & issue all hit loads
//      first (MLP up to 16 LDG.128), consume afterwards -> one exposed
//      DRAM stall instead of up to four.
//   B. folding butterfly: each stage halves channel responsibility
//      (16 SHFLs total vs 80); channel c ends on even lane with
//      c = 8*b4 + 4*b3 + 2*b2 + b1 of the lane index.
// Window unchanged: W_CUT=-12.5, HW=5 (measured rel_err 5.4e-6, 185x slack).

#define W_CUT (-12.5f)   // exp(-12.5) ~ 3.7e-6
#define HW 5             // window half-width -> 11x11 = 121 candidates
#define NCAND ((2*HW + 1) * (2*HW + 1))   // 121

__global__ void zero_kernel(float* out, int n) {
    int i = blockIdx.x * blockDim.x + threadIdx.x;
    if (i < n) out[i] = 0.0f;
}

__global__ __launch_bounds__(32) void ray_tube_kernel(
    const float* __restrict__ mem,   // [128^3, 16]
    const float* __restrict__ ro,    // [32, 3]
    const float* __restrict__ rd,    // [32, 3] unit vectors
    float* __restrict__ out)         // [32, 16]
{
    const int b     = blockIdx.y;
    const int slice = blockIdx.x;
    const int lane  = threadIdx.x;   // 0..31

    const float ox = ro[3*b + 0], oy = ro[3*b + 1], oz = ro[3*b + 2];
    const float ddx = rd[3*b + 0], ddy = rd[3*b + 1], ddz = rd[3*b + 2];

    // dominant axis of the direction (|d_a| >= 1/sqrt(3))
    float ax = fabsf(ddx), ay = fabsf(ddy), az = fabsf(ddz);
    int a = 0; float da = ddx; float amax = ax;
    if (ay > amax) { a = 1; da = ddy; amax = ay; }
    if (az > amax) { a = 2; da = ddz; amax = az; }

    // line/plane intersection parameter and point (block-uniform)
    const float oa = (a == 0) ? ox : ((a == 1) ? oy : oz);
    const float tc = ((float)slice - oa) / da;

    // positive-t decay kill: in-plane offset <= sqrt(2)*5 + rounding < 8;
    // if tc - 8 > 25 then w <= -0.5*t < -12.5 even at r2 = 0. (uniform exit)
    if (tc - 8.0f > 25.0f) return;

    const float cx = fmaf(tc, ddx, ox);
    const float cy = fmaf(tc, ddy, oy);
    const float cz = fmaf(tc, ddz, oz);

    float cu, cv;
    if (a == 0)      { cu = cy; cv = cz; }
    else if (a == 1) { cu = cx; cv = cz; }
    else             { cu = cx; cv = cy; }

    const int cu0 = __float2int_rn(cu);
    const int cv0 = __float2int_rn(cv);
    // window entirely outside the grid in-plane (uniform exit)
    if (cu0 + HW < 0 || cu0 - HW > 127) return;
    if (cv0 + HW < 0 || cv0 - HW > 127) return;

    // ---- phase 1: weights + hit loads (no consumption -> loads overlap) ----
    float  kk[4] = {0.0f, 0.0f, 0.0f, 0.0f};
    float4 v0[4], v1[4], v2[4], v3[4];   // consumed only when kk[j] != 0

    #pragma unroll
    for (int j = 0; j < 4; j++) {
        const int idx = lane + j * 32;
        if (idx < NCAND) {
            const int iu = cu0 - HW + idx / (2*HW + 1);
            const int iv = cv0 - HW + idx % (2*HW + 1);
            if (iu >= 0 && iu <= 127 && iv >= 0 && iv <= 127) {
                int x, y, z;
                if (a == 0)      { x = slice; y = iu;    z = iv;    }
                else if (a == 1) { x = iu;    y = slice; z = iv;    }
                else             { x = iu;    y = iv;    z = slice; }

                // residual form, matching the reference's formula exactly
                const float fx = (float)x - ox;
                const float fy = (float)y - oy;
                const float fz = (float)z - oz;
                const float t  = fx*ddx + fy*ddy + fz*ddz;
                const float rx = fmaf(-t, ddx, fx);
                const float ry = fmaf(-t, ddy, fy);
                const float rz = fmaf(-t, ddz, fz);
                const float r2 = rx*rx + ry*ry + rz*rz;
                const float w  = -2.0f * r2 - 0.5f * fmaxf(t, 0.0f);

                if (w > W_CUT) {
                    kk[j] = __expf(w);
                    const size_t n = (size_t)((x << 14) + (y << 7) + z);
                    const float4* m = (const float4*)(mem + n * 16);
                    v0[j] = m[0]; v1[j] = m[1]; v2[j] = m[2]; v3[j] = m[3];
                }
            }
        }
    }

    // ---- phase 2: consume ----
    float acc[16];
    #pragma unroll
    for (int c = 0; c < 16; c++) acc[c] = 0.0f;

    #pragma unroll
    for (int j = 0; j < 4; j++) {
        if (kk[j] != 0.0f) {
            const float k = kk[j];
            acc[0]  = fmaf(k, v0[j].x, acc[0]);   acc[1]  = fmaf(k, v0[j].y, acc[1]);
            acc[2]  = fmaf(k, v0[j].z, acc[2]);   acc[3]  = fmaf(k, v0[j].w, acc[3]);
            acc[4]  = fmaf(k, v1[j].x, acc[4]);   acc[5]  = fmaf(k, v1[j].y, acc[5]);
            acc[6]  = fmaf(k, v1[j].z, acc[6]);   acc[7]  = fmaf(k, v1[j].w, acc[7]);
            acc[8]  = fmaf(k, v2[j].x, acc[8]);   acc[9]  = fmaf(k, v2[j].y, acc[9]);
            acc[10] = fmaf(k, v2[j].z, acc[10]);  acc[11] = fmaf(k, v2[j].w, acc[11]);
            acc[12] = fmaf(k, v3[j].x, acc[12]);  acc[13] = fmaf(k, v3[j].y, acc[13]);
            acc[14] = fmaf(k, v3[j].z, acc[14]);  acc[15] = fmaf(k, v3[j].w, acc[15]);
        }
    }

    // ---- folding butterfly: halve channel responsibility each stage ----
    // stage A (off=16): 8 channels per lane
    {
        const bool hi = (lane & 16) != 0;
        float act[8];
        #pragma unroll
        for (int j = 0; j < 8; j++) {
            const float send = hi ? acc[j] : acc[j + 8];
            const float keep = hi ? acc[j + 8] : acc[j];
            act[j] = keep + __shfl_xor_sync(0xFFFFFFFFu, send, 16);
        }
        // stage B (off=8): 4 channels
        const bool h3 = (lane & 8) != 0;
        float actB[4];
        #pragma unroll
        for (int j = 0; j < 4; j++) {
            const float send = h3 ? act[j] : act[j + 4];
            const float keep = h3 ? act[j + 4] : act[j];
            actB[j] = keep + __shfl_xor_sync(0xFFFFFFFFu, send, 8);
        }
        // stage C (off=4): 2 channels
        const bool h2 = (lane & 4) != 0;
        float actC[2];
        #pragma unroll
        for (int j = 0; j < 2; j++) {
            const float send = h2 ? actB[j] : actB[j + 2];
            const float keep = h2 ? actB[j + 2] : actB[j];
            actC[j] = keep + __shfl_xor_sync(0xFFFFFFFFu, send, 4);
        }
        // stage D (off=2): 1 channel
        const bool h1 = (lane & 2) != 0;
        const float sendD = h1 ? actC[0] : actC[1];
        const float keepD = h1 ? actC[1] : actC[0];
        float actD = keepD + __shfl_xor_sync(0xFFFFFFFFu, sendD, 2);
        // stage E (off=1): pair-combine (both lanes end with the full sum)
        actD += __shfl_xor_sync(0xFFFFFFFFu, actD, 1);

        // channel owned by this lane: c = 8*b4 + 4*b3 + 2*b2 + 1*b1
        if ((lane & 1) == 0) {
            const int c = ((lane >> 4) & 1) * 8 + ((lane >> 3) & 1) * 4 +
                          ((lane >> 2) & 1) * 2 + ((lane >> 1) & 1);
            if (actD != 0.0f) atomicAdd(&out[b * 16 + c], actD);
        }
    }
}

extern "C" void kernel_launch(void* const* d_in, const int* in_sizes, int n_in,
                              void* d_out, int out_size) {
    const float* mem = (const float*)d_in[0];
    // d_in[1] is the coordinate meshgrid -- deterministic, recomputed from
    // indices on the fly, never read.
    const float* ro  = (const float*)d_in[2];
    const float* rd  = (const float*)d_in[3];
    float* out = (float*)d_out;

    zero_kernel<<<1, 512>>>(out, out_size);   // d_out is poisoned to 0xAA

    dim3 g(128, 32);   // (slice along dominant axis, ray)
    ray_tube_kernel<<<g, 32>>>(mem, ro, rd, out);
}